// round 1
// baseline (speedup 1.0000x reference)
#include <cuda_runtime.h>
#include <math.h>

#define BATCH 8192
#define DIM   128
#define BM    128
#define BN    128
#define SPLITS 2
#define COLS_PER_SPLIT (BATCH / SPLITS)
#define NTILES (COLS_PER_SPLIT / BN)
#define THREADS 256

#define THRESH_F 0.5f
#define MARGIN_F 0.1f
#define ONE_M_EPS 0.99999f

__device__ float g_minpos[SPLITS * BATCH];
__device__ float g_maxneg[SPLITS * BATCH];
__device__ float g_possum[SPLITS * BATCH];
__device__ float g_negsum[SPLITS * BATCH];

__device__ __forceinline__ float inf_f() { return __int_as_float(0x7f800000); }

// Load a 128x128 f32 tile (rows [base, base+128) of F) into smem transposed
// to [k][m] layout with an XOR granule swizzle:
//   element (k, m) lives at S[k*128 + ((mg ^ (k>>2)) * 4 + (m&3))], mg = m>>2.
// Loaded via 4x4 register transpose: coalesced LDG.128, conflict-free STS.128.
__device__ __forceinline__ void load_tile_T(const float4* __restrict__ F4,
                                            int base, float* __restrict__ S,
                                            int tid) {
#pragma unroll
    for (int i = 0; i < 4; i++) {
        int fl = i * THREADS + tid;
        int rg = fl >> 5;      // row-group (4 rows), 0..31
        int kq = fl & 31;      // k granule, 0..31
        const int RW = DIM / 4;
        float4 r0 = F4[(base + rg * 4 + 0) * RW + kq];
        float4 r1 = F4[(base + rg * 4 + 1) * RW + kq];
        float4 r2 = F4[(base + rg * 4 + 2) * RW + kq];
        float4 r3 = F4[(base + rg * 4 + 3) * RW + kq];
        int g = ((rg ^ kq) << 2);
        *(float4*)&S[(kq * 4 + 0) * DIM + g] = make_float4(r0.x, r1.x, r2.x, r3.x);
        *(float4*)&S[(kq * 4 + 1) * DIM + g] = make_float4(r0.y, r1.y, r2.y, r3.y);
        *(float4*)&S[(kq * 4 + 2) * DIM + g] = make_float4(r0.z, r1.z, r2.z, r3.z);
        *(float4*)&S[(kq * 4 + 3) * DIM + g] = make_float4(r0.w, r1.w, r2.w, r3.w);
    }
}

// PASS 0: per-row min over positives / max over negatives.
// PASS 1: per-row masked exp-sums using combined min/max from pass 0.
template <int PASS>
__global__ __launch_bounds__(THREADS, 1)
void ms_pass(const float* __restrict__ F, const int* __restrict__ L) {
    extern __shared__ float sm[];
    float* As = sm;                  // [128][128] swizzled, row tile
    float* Bs = sm + DIM * DIM;      // [128][128] swizzled, col tile
    int*   labc = (int*)(sm + 2 * DIM * DIM);  // [128] col labels

    const int tid = threadIdx.x;
    const int tm = tid >> 4;     // 0..15
    const int tn = tid & 15;     // 0..15
    const int rowBase = blockIdx.x * BM;
    const int split = blockIdx.y;
    const int colStart = split * COLS_PER_SPLIT;
    const float4* F4 = (const float4*)F;

    load_tile_T(F4, rowBase, As, tid);

    int rlab[8];
#pragma unroll
    for (int i = 0; i < 8; i++) rlab[i] = L[rowBase + tm * 8 + i];

    float st0[8], st1[8];        // pass0: minpos/maxneg ; pass1: possum/negsum
    float rmn[8], rmx[8];
#pragma unroll
    for (int i = 0; i < 8; i++) {
        if (PASS == 0) {
            st0[i] = inf_f();
            st1[i] = -inf_f();
        } else {
            st0[i] = 0.0f;
            st1[i] = 0.0f;
            int r = rowBase + tm * 8 + i;
            float mn = inf_f(), mx = -inf_f();
#pragma unroll
            for (int s = 0; s < SPLITS; s++) {
                mn = fminf(mn, g_minpos[s * BATCH + r]);
                mx = fmaxf(mx, g_maxneg[s * BATCH + r]);
            }
            rmn[i] = mn;
            rmx[i] = mx;
        }
    }

    for (int t = 0; t < NTILES; t++) {
        int colBase = colStart + t * BN;
        __syncthreads();  // protect Bs/labc from previous tile's readers
        load_tile_T(F4, colBase, Bs, tid);
        if (tid < BN) labc[tid] = L[colBase + tid];
        __syncthreads();

        float acc[8][8];
#pragma unroll
        for (int i = 0; i < 8; i++)
#pragma unroll
            for (int j = 0; j < 8; j++) acc[i][j] = 0.0f;

#pragma unroll 4
        for (int k = 0; k < DIM; k++) {
            int kq = k >> 2;
            float4 a0 = *(const float4*)&As[k * DIM + (((tm * 2) ^ kq) << 2)];
            float4 a1 = *(const float4*)&As[k * DIM + (((tm * 2 + 1) ^ kq) << 2)];
            float4 b0 = *(const float4*)&Bs[k * DIM + (((tn * 2) ^ kq) << 2)];
            float4 b1 = *(const float4*)&Bs[k * DIM + (((tn * 2 + 1) ^ kq) << 2)];
            float a[8] = {a0.x, a0.y, a0.z, a0.w, a1.x, a1.y, a1.z, a1.w};
            float b[8] = {b0.x, b0.y, b0.z, b0.w, b1.x, b1.y, b1.z, b1.w};
#pragma unroll
            for (int i = 0; i < 8; i++)
#pragma unroll
                for (int j = 0; j < 8; j++)
                    acc[i][j] = fmaf(a[i], b[j], acc[i][j]);
        }

        int cl[8];
#pragma unroll
        for (int j = 0; j < 8; j++) cl[j] = labc[tn * 8 + j];

#pragma unroll
        for (int i = 0; i < 8; i++) {
            int gi = rowBase + tm * 8 + i;
#pragma unroll
            for (int j = 0; j < 8; j++) {
                int gj = colBase + tn * 8 + j;
                float sim = acc[i][j];
                bool same = (rlab[i] == cl[j]);
                if (PASS == 0) {
                    if (same) {
                        if (gi != gj && sim < ONE_M_EPS)
                            st0[i] = fminf(st0[i], sim);
                    } else {
                        st1[i] = fmaxf(st1[i], sim);
                    }
                } else {
                    if (!same) {
                        if (sim + MARGIN_F > rmn[i])
                            st1[i] += __expf(40.0f * (sim - THRESH_F));
                    } else if (gi != gj && sim < ONE_M_EPS) {
                        if (sim - MARGIN_F < rmx[i])
                            st0[i] += __expf(-2.0f * (sim - THRESH_F));
                    }
                }
            }
        }
    }

    // Block reduction across the 16 tn-threads sharing each row.
    __syncthreads();                 // everyone done with As before reuse
    float* red0 = As;                // [16][128]
    float* red1 = As + 16 * 128;     // [16][128]
#pragma unroll
    for (int i = 0; i < 8; i++) {
        red0[tn * 128 + tm * 8 + i] = st0[i];
        red1[tn * 128 + tm * 8 + i] = st1[i];
    }
    __syncthreads();
    if (tid < BM) {
        if (PASS == 0) {
            float mn = inf_f(), mx = -inf_f();
#pragma unroll
            for (int s = 0; s < 16; s++) {
                mn = fminf(mn, red0[s * 128 + tid]);
                mx = fmaxf(mx, red1[s * 128 + tid]);
            }
            g_minpos[split * BATCH + rowBase + tid] = mn;
            g_maxneg[split * BATCH + rowBase + tid] = mx;
        } else {
            float ps = 0.0f, ns = 0.0f;
#pragma unroll
            for (int s = 0; s < 16; s++) {
                ps += red0[s * 128 + tid];
                ns += red1[s * 128 + tid];
            }
            g_possum[split * BATCH + rowBase + tid] = ps;
            g_negsum[split * BATCH + rowBase + tid] = ns;
        }
    }
}

__global__ void ms_final(float* __restrict__ out) {
    __shared__ float red[256];
    float local = 0.0f;
    for (int r = threadIdx.x; r < BATCH; r += 256) {
        float mn = inf_f(), mx = -inf_f(), ps = 0.0f, ns = 0.0f;
#pragma unroll
        for (int s = 0; s < SPLITS; s++) {
            mn = fminf(mn, g_minpos[s * BATCH + r]);
            mx = fmaxf(mx, g_maxneg[s * BATCH + r]);
            ps += g_possum[s * BATCH + r];
            ns += g_negsum[s * BATCH + r];
        }
        bool has_pos = (mn < inf_f());
        bool has_neg = (mx > -inf_f());
        bool sel = (mn - MARGIN_F < mx);  // == has_neg_sel == has_pos_sel
        if (has_pos && has_neg && sel)
            local += 0.5f * log1pf(ps) + 0.025f * log1pf(ns);
    }
    red[threadIdx.x] = local;
    __syncthreads();
#pragma unroll
    for (int s = 128; s > 0; s >>= 1) {
        if (threadIdx.x < s) red[threadIdx.x] += red[threadIdx.x + s];
        __syncthreads();
    }
    if (threadIdx.x == 0) out[0] = red[0];
}

extern "C" void kernel_launch(void* const* d_in, const int* in_sizes, int n_in,
                              void* d_out, int out_size) {
    const float* F = (const float*)d_in[0];
    const int* L = (const int*)d_in[1];
    if (n_in >= 2 && in_sizes[0] == BATCH) {  // defensive: inputs swapped
        F = (const float*)d_in[1];
        L = (const int*)d_in[0];
    }

    size_t smem = (size_t)(2 * DIM * DIM) * sizeof(float) + BN * sizeof(int);
    cudaFuncSetAttribute((const void*)ms_pass<0>,
                         cudaFuncAttributeMaxDynamicSharedMemorySize, (int)smem);
    cudaFuncSetAttribute((const void*)ms_pass<1>,
                         cudaFuncAttributeMaxDynamicSharedMemorySize, (int)smem);

    dim3 grid(BATCH / BM, SPLITS);
    ms_pass<0><<<grid, THREADS, smem>>>(F, L);
    ms_pass<1><<<grid, THREADS, smem>>>(F, L);
    ms_final<<<1, 256>>>((float*)d_out);
}

// round 3
// speedup vs baseline: 5.1585x; 5.1585x over previous
#include <cuda_runtime.h>
#include <cuda_bf16.h>
#include <math.h>
#include <cstdint>

#define BATCH 8192
#define DIM   128
#define BM    128
#define BN    128
#define SPLITS 2
#define COLS_PER_SPLIT (BATCH / SPLITS)
#define NT (COLS_PER_SPLIT / BN)   // 32 col tiles per CTA
#define THREADS 256

#define MARGIN_F 0.1f
#define ONE_M_EPS 0.99999f
#define LOG2E 1.44269504089f

// exp2 poly coeffs (|f|<=0.5, rel err ~3e-6)
#define EC1 0.69314718056f
#define EC2 0.240226506959f
#define EC3 0.0555041086648f
#define EC4 0.00961812910763f
#define EC5 0.00133335581464f

// arg = scale*(sim-0.5)*log2e -> sim*A + B
#define A_POS (-2.0f * LOG2E)
#define B_POS (LOG2E)
#define A_NEG (40.0f * LOG2E)
#define B_NEG (-20.0f * LOG2E)

__device__ __nv_bfloat16 g_fb[BATCH * DIM];
__device__ float g_minpos[SPLITS * BATCH];
__device__ float g_maxneg[SPLITS * BATCH];
__device__ float g_possum[SPLITS * BATCH];
__device__ float g_negsum[SPLITS * BATCH];

__device__ __forceinline__ float inf_f() { return __int_as_float(0x7f800000); }

__device__ __forceinline__ uint32_t smem_to_u32(const void* p) {
    uint32_t a;
    asm("{ .reg .u64 t; cvta.to.shared.u64 t, %1; cvt.u32.u64 %0, t; }"
        : "=r"(a) : "l"(p));
    return a;
}

__device__ __forceinline__ void ldsm_x4(uint32_t (&r)[4], uint32_t addr) {
    asm volatile("ldmatrix.sync.aligned.m8n8.x4.shared.b16 {%0,%1,%2,%3}, [%4];"
                 : "=r"(r[0]), "=r"(r[1]), "=r"(r[2]), "=r"(r[3]) : "r"(addr));
}

__device__ __forceinline__ void mma_bf16(float (&d)[4], const uint32_t (&a)[4],
                                         uint32_t b0, uint32_t b1) {
    asm volatile("mma.sync.aligned.m16n8k16.row.col.f32.bf16.bf16.f32 "
                 "{%0,%1,%2,%3}, {%4,%5,%6,%7}, {%8,%9}, {%0,%1,%2,%3};"
                 : "+f"(d[0]), "+f"(d[1]), "+f"(d[2]), "+f"(d[3])
                 : "r"(a[0]), "r"(a[1]), "r"(a[2]), "r"(a[3]), "r"(b0), "r"(b1));
}

#define CP_ASYNC16(sa, g) \
    asm volatile("cp.async.cg.shared.global [%0], [%1], 16;" :: "r"(sa), "l"(g) : "memory")
#define CP_COMMIT() asm volatile("cp.async.commit_group;" ::: "memory")
#define CP_WAIT0()  asm volatile("cp.async.wait_group 0;" ::: "memory")

// smem byte offsets
#define OFF_A   0
#define OFF_B0  32768
#define OFF_B1  65536
#define OFF_LAB 98304      // int labc[2][128]
#define SMEM_BYTES 99328

__device__ __forceinline__ float exp2p(float tt) {
    float z = tt + 12582912.0f;
    int ni = __float_as_int(z) - 0x4B400000;
    float fn = z - 12582912.0f;
    float f = tt - fn;
    float p = fmaf(f, EC5, EC4);
    p = fmaf(f, p, EC3);
    p = fmaf(f, p, EC2);
    p = fmaf(f, p, EC1);
    p = fmaf(f, p, 1.0f);
    return p * __int_as_float((ni + 127) << 23);
}

__global__ void prep_bf16(const float* __restrict__ F) {
    int idx = blockIdx.x * blockDim.x + threadIdx.x;   // 262144 threads, 4 floats each
    float4 v = ((const float4*)F)[idx];
    ((__nv_bfloat162*)g_fb)[idx * 2]     = __floats2bfloat162_rn(v.x, v.y);
    ((__nv_bfloat162*)g_fb)[idx * 2 + 1] = __floats2bfloat162_rn(v.z, v.w);
}

// Prefetch a 128x128 bf16 tile (rows [base,+128) of g_fb) into smem,
// 256B rows, 16B chunks XOR-swizzled by (row&7).
__device__ __forceinline__ void prefetch_tile(const __nv_bfloat16* src,
                                              uint32_t dstBase, int tid) {
#pragma unroll
    for (int i = 0; i < 8; i++) {
        int idx = tid + i * THREADS;       // 0..2047
        int r = idx >> 4, c = idx & 15;
        uint32_t sa = dstBase + r * 256 + ((c ^ (r & 7)) << 4);
        CP_ASYNC16(sa, (const char*)src + r * 256 + c * 16);
    }
}

template <int PASS>
__global__ __launch_bounds__(THREADS, 1)
void ms_pass(const int* __restrict__ L) {
    extern __shared__ char smem[];
    const uint32_t sb = smem_to_u32(smem);
    const int tid = threadIdx.x;
    const int lane = tid & 31;
    const int w = tid >> 5;
    const int wm = w >> 2, wn = w & 3;   // warp tile: rows wm*64, cols wn*32
    const int rowBase = blockIdx.x * BM;
    const int split = blockIdx.y;
    const int colStart = split * COLS_PER_SPLIT;

    // prologue: A tile + B tile 0 + labels 0
    prefetch_tile(g_fb + (size_t)rowBase * DIM, sb + OFF_A, tid);
    prefetch_tile(g_fb + (size_t)colStart * DIM, sb + OFF_B0, tid);
    if (tid < 32) CP_ASYNC16(sb + OFF_LAB + tid * 16, L + colStart + tid * 4);
    CP_COMMIT();

    // per-thread row state (8 rows: 4 mtiles x {r, r+8})
    int gi[8], rl[8];
    float s0[8], s1[8], pthr[8], nthr[8];
#pragma unroll
    for (int mt = 0; mt < 4; mt++)
#pragma unroll
        for (int h = 0; h < 2; h++) {
            int i = mt * 2 + h;
            int row_l = wm * 64 + mt * 16 + (lane >> 2) + h * 8;
            gi[i] = rowBase + row_l;
            rl[i] = L[gi[i]];
            if (PASS == 0) {
                s0[i] = inf_f();
                s1[i] = -inf_f();
            } else {
                s0[i] = 0.0f;
                s1[i] = 0.0f;
                float mn = fminf(g_minpos[gi[i]], g_minpos[BATCH + gi[i]]);
                float mx = fmaxf(g_maxneg[gi[i]], g_maxneg[BATCH + gi[i]]);
                pthr[i] = fminf(ONE_M_EPS, mx + MARGIN_F);
                nthr[i] = mn - MARGIN_F;
            }
        }

    // ldmatrix address components
    uint32_t aAddr[4], aSw[4], bRow[2], bSw[2];
    const int khA = lane >> 4;            // k-half for A
    const int khB = (lane >> 3) & 1;      // k-half for B
#pragma unroll
    for (int mt = 0; mt < 4; mt++) {
        int r = wm * 64 + mt * 16 + (lane & 15);
        aAddr[mt] = sb + OFF_A + r * 256;
        aSw[mt] = r & 7;
    }
#pragma unroll
    for (int p = 0; p < 2; p++) {
        int r = wn * 32 + p * 16 + ((lane >> 4) << 3) + (lane & 7);
        bRow[p] = r * 256;
        bSw[p] = r & 7;
    }

    for (int t = 0; t < NT; t++) {
        CP_WAIT0();
        __syncthreads();   // B[cbuf]/labels visible; all warps done with B[nbuf]
        const int cbuf = t & 1;
        const int colBase = colStart + t * BN;
        if (t + 1 < NT) {
            prefetch_tile(g_fb + (size_t)(colBase + BN) * DIM,
                          sb + (cbuf ? OFF_B0 : OFF_B1), tid);
            if (tid < 32)
                CP_ASYNC16(sb + OFF_LAB + (cbuf ? 0 : 512) + tid * 16,
                           L + colBase + BN + tid * 4);
            CP_COMMIT();
        }
        const uint32_t bBase = sb + (cbuf ? OFF_B1 : OFF_B0);

        float d[4][4][4];
#pragma unroll
        for (int mt = 0; mt < 4; mt++)
#pragma unroll
            for (int nt = 0; nt < 4; nt++)
#pragma unroll
                for (int r = 0; r < 4; r++) d[mt][nt][r] = 0.0f;

#pragma unroll
        for (int ks = 0; ks < 8; ks++) {
            uint32_t a[4][4], bb[2][4];
#pragma unroll
            for (int mt = 0; mt < 4; mt++)
                ldsm_x4(a[mt], aAddr[mt] + (((2 * ks + khA) ^ aSw[mt]) << 4));
#pragma unroll
            for (int p = 0; p < 2; p++)
                ldsm_x4(bb[p], bBase + bRow[p] + (((2 * ks + khB) ^ bSw[p]) << 4));
#pragma unroll
            for (int mt = 0; mt < 4; mt++)
#pragma unroll
                for (int nt = 0; nt < 4; nt++)
                    mma_bf16(d[mt][nt], a[mt], bb[nt >> 1][(nt & 1) * 2],
                             bb[nt >> 1][(nt & 1) * 2 + 1]);
        }

        // epilogue straight from register accumulators
        const int* labc = (const int*)(smem + OFF_LAB + cbuf * 512);
        int cl[8], cg[8];
#pragma unroll
        for (int nt = 0; nt < 4; nt++)
#pragma unroll
            for (int j = 0; j < 2; j++) {
                int col_l = wn * 32 + nt * 8 + 2 * (lane & 3) + j;
                cl[nt * 2 + j] = labc[col_l];
                cg[nt * 2 + j] = colBase + col_l;
            }
#pragma unroll
        for (int mt = 0; mt < 4; mt++)
#pragma unroll
            for (int nt = 0; nt < 4; nt++)
#pragma unroll
                for (int rix = 0; rix < 4; rix++) {
                    int h = rix >> 1, j = rix & 1;
                    int i = mt * 2 + h, cj = nt * 2 + j;
                    float sim = d[mt][nt][rix];
                    bool same = (rl[i] == cl[cj]);
                    if (PASS == 0) {
                        bool pk = same && (sim < ONE_M_EPS) && (cg[cj] != gi[i]);
                        if (pk) s0[i] = fminf(s0[i], sim);
                        if (!same) s1[i] = fmaxf(s1[i], sim);
                    } else {
                        float e = exp2p(fmaf(sim, same ? A_POS : A_NEG,
                                             same ? B_POS : B_NEG));
                        bool okp = same && (sim < pthr[i]) && (cg[cj] != gi[i]);
                        bool okn = (!same) && (sim > nthr[i]);
                        s0[i] += okp ? e : 0.0f;
                        s1[i] += okn ? e : 0.0f;
                    }
                }
    }

    // reduction: shfl over the 4 col-lanes, then smem over the 4 col-warps
    __syncthreads();
    float* red0 = (float*)smem;          // [4][128]
    float* red1 = red0 + 512;
#pragma unroll
    for (int i = 0; i < 8; i++) {
        float v0 = s0[i], v1 = s1[i];
#pragma unroll
        for (int m = 1; m <= 2; m <<= 1) {
            float o0 = __shfl_xor_sync(0xffffffff, v0, m);
            float o1 = __shfl_xor_sync(0xffffffff, v1, m);
            if (PASS == 0) {
                v0 = fminf(v0, o0);
                v1 = fmaxf(v1, o1);
            } else {
                v0 += o0;
                v1 += o1;
            }
        }
        if ((lane & 3) == 0) {
            int mt = i >> 1, h = i & 1;
            int row_l = wm * 64 + mt * 16 + (lane >> 2) + h * 8;
            red0[wn * 128 + row_l] = v0;
            red1[wn * 128 + row_l] = v1;
        }
    }
    __syncthreads();
    if (tid < BM) {
        if (PASS == 0) {
            float mn = fminf(fminf(red0[tid], red0[128 + tid]),
                             fminf(red0[256 + tid], red0[384 + tid]));
            float mx = fmaxf(fmaxf(red1[tid], red1[128 + tid]),
                             fmaxf(red1[256 + tid], red1[384 + tid]));
            g_minpos[split * BATCH + rowBase + tid] = mn;
            g_maxneg[split * BATCH + rowBase + tid] = mx;
        } else {
            g_possum[split * BATCH + rowBase + tid] =
                red0[tid] + red0[128 + tid] + red0[256 + tid] + red0[384 + tid];
            g_negsum[split * BATCH + rowBase + tid] =
                red1[tid] + red1[128 + tid] + red1[256 + tid] + red1[384 + tid];
        }
    }
}

__global__ void ms_final(float* __restrict__ out) {
    __shared__ float red[256];
    float local = 0.0f;
    for (int r = threadIdx.x; r < BATCH; r += 256) {
        float mn = fminf(g_minpos[r], g_minpos[BATCH + r]);
        float mx = fmaxf(g_maxneg[r], g_maxneg[BATCH + r]);
        float ps = g_possum[r] + g_possum[BATCH + r];
        float ns = g_negsum[r] + g_negsum[BATCH + r];
        bool has_pos = (mn < inf_f());
        bool has_neg = (mx > -inf_f());
        bool sel = (mn - MARGIN_F < mx);   // == has_neg_sel == has_pos_sel
        if (has_pos && has_neg && sel)
            local += 0.5f * log1pf(ps) + 0.025f * log1pf(ns);
    }
    red[threadIdx.x] = local;
    __syncthreads();
#pragma unroll
    for (int s = 128; s > 0; s >>= 1) {
        if (threadIdx.x < s) red[threadIdx.x] += red[threadIdx.x + s];
        __syncthreads();
    }
    if (threadIdx.x == 0) out[0] = red[0];
}

extern "C" void kernel_launch(void* const* d_in, const int* in_sizes, int n_in,
                              void* d_out, int out_size) {
    const float* F = (const float*)d_in[0];
    const int* L = (const int*)d_in[1];
    if (n_in >= 2 && in_sizes[0] == BATCH) {  // defensive: inputs swapped
        F = (const float*)d_in[1];
        L = (const int*)d_in[0];
    }

    cudaFuncSetAttribute(ms_pass<0>, cudaFuncAttributeMaxDynamicSharedMemorySize, SMEM_BYTES);
    cudaFuncSetAttribute(ms_pass<1>, cudaFuncAttributeMaxDynamicSharedMemorySize, SMEM_BYTES);

    prep_bf16<<<1024, 256>>>(F);
    dim3 grid(BATCH / BM, SPLITS);
    ms_pass<0><<<grid, THREADS, SMEM_BYTES>>>(L);
    ms_pass<1><<<grid, THREADS, SMEM_BYTES>>>(L);
    ms_final<<<1, 256>>>((float*)d_out);
}

// round 4
// speedup vs baseline: 6.6166x; 1.2827x over previous
#include <cuda_runtime.h>
#include <cuda_bf16.h>
#include <math.h>
#include <cstdint>

#define BATCH 8192
#define DIM   128
#define NROWT 64                 // 8192/128 row blocks
#define NTILES_TRI 2080          // 64*65/2 triangle tiles
#define GRID_MAIN 148
#define THREADS 256

#define MARGIN_F 0.1f
#define ONE_M_EPS 0.99999f
#define LOG2E 1.44269504089f
// arg = scale*(sim-0.5)*log2e -> sim*A + B
#define A_POS (-2.0f * LOG2E)
#define B_POS (LOG2E)
#define A_NEG (40.0f * LOG2E)
#define B_NEG (-20.0f * LOG2E)

__device__ __nv_bfloat16 g_fb[BATCH * DIM];
__device__ unsigned int g_min_enc[BATCH];   // encoded float, atomicMin
__device__ unsigned int g_max_enc[BATCH];   // encoded float, atomicMax
__device__ float g_possum[BATCH];
__device__ float g_negsum[BATCH];

__device__ __forceinline__ float inf_f() { return __int_as_float(0x7f800000); }
__device__ __forceinline__ unsigned enc_f(float x) {
    unsigned u = __float_as_uint(x);
    return (u & 0x80000000u) ? ~u : (u | 0x80000000u);
}
__device__ __forceinline__ float dec_f(unsigned e) {
    return __uint_as_float((e & 0x80000000u) ? (e & 0x7FFFFFFFu) : ~e);
}
__device__ __forceinline__ float ex2f(float x) {
    float r;
    asm("ex2.approx.f32 %0, %1;" : "=f"(r) : "f"(x));
    return r;
}
__device__ __forceinline__ uint32_t smem_to_u32(const void* p) {
    uint32_t a;
    asm("{ .reg .u64 t; cvta.to.shared.u64 t, %1; cvt.u32.u64 %0, t; }"
        : "=r"(a) : "l"(p));
    return a;
}
__device__ __forceinline__ void ldsm_x4(uint32_t (&r)[4], uint32_t addr) {
    asm volatile("ldmatrix.sync.aligned.m8n8.x4.shared.b16 {%0,%1,%2,%3}, [%4];"
                 : "=r"(r[0]), "=r"(r[1]), "=r"(r[2]), "=r"(r[3]) : "r"(addr));
}
__device__ __forceinline__ void mma_bf16(float (&d)[4], const uint32_t (&a)[4],
                                         uint32_t b0, uint32_t b1) {
    asm volatile("mma.sync.aligned.m16n8k16.row.col.f32.bf16.bf16.f32 "
                 "{%0,%1,%2,%3}, {%4,%5,%6,%7}, {%8,%9}, {%0,%1,%2,%3};"
                 : "+f"(d[0]), "+f"(d[1]), "+f"(d[2]), "+f"(d[3])
                 : "r"(a[0]), "r"(a[1]), "r"(a[2]), "r"(a[3]), "r"(b0), "r"(b1));
}
#define CP_ASYNC16(sa, g) \
    asm volatile("cp.async.cg.shared.global [%0], [%1], 16;" :: "r"(sa), "l"(g) : "memory")
#define CP_COMMIT() asm volatile("cp.async.commit_group;" ::: "memory")
#define CP_WAIT0()  asm volatile("cp.async.wait_group 0;" ::: "memory")

// ---- smem layout (bytes) ----
#define OFF_A0   0
#define OFF_A1   32768
#define OFF_B0   65536
#define OFF_B1   98304
#define OFF_LABA 131072      // [2][128] int
#define OFF_LABB 132096      // [2][128] int
#define OFF_TPR  133120      // float[128]
#define OFF_TNR  133632
#define OFF_TPC  134144
#define OFF_TNC  134656
#define OFF_RR0  135168      // float[4][128]
#define OFF_RR1  137216      // float[4][128]
#define OFF_RC0  139264      // float[2][128]
#define OFF_RC1  140288      // float[2][128]
#define SMEM_BYTES 141312

// 128x128 bf16 tile -> smem, 256B rows, 16B chunks XOR-swizzled by (row&7)
__device__ __forceinline__ void prefetch_tile(const __nv_bfloat16* src,
                                              uint32_t dstBase, int tid) {
#pragma unroll
    for (int i = 0; i < 8; i++) {
        int idx = tid + i * THREADS;
        int r = idx >> 4, c = idx & 15;
        uint32_t sa = dstBase + r * 256 + ((c ^ (r & 7)) << 4);
        CP_ASYNC16(sa, (const char*)src + r * 256 + c * 16);
    }
}

__device__ __forceinline__ void decode_tile(int k, int& ti, int& tj) {
    int a = (int)((sqrtf(8.0f * (float)k + 1.0f) - 1.0f) * 0.5f);
    while ((a + 1) * (a + 2) / 2 <= k) ++a;
    while (a * (a + 1) / 2 > k) --a;
    tj = a;
    ti = k - a * (a + 1) / 2;   // ti <= tj
}

__device__ __forceinline__ void prefetch_pair(int ti, int tj, int buf,
                                              uint32_t sb, const int* L, int tid) {
    prefetch_tile(g_fb + (size_t)ti * 128 * DIM, sb + (buf ? OFF_A1 : OFF_A0), tid);
    prefetch_tile(g_fb + (size_t)tj * 128 * DIM, sb + (buf ? OFF_B1 : OFF_B0), tid);
    if (tid < 32)
        CP_ASYNC16(sb + OFF_LABA + buf * 512 + tid * 16, L + ti * 128 + tid * 4);
    else if (tid < 64)
        CP_ASYNC16(sb + OFF_LABB + buf * 512 + (tid - 32) * 16, L + tj * 128 + (tid - 32) * 4);
}

__global__ void prep_k(const float* __restrict__ F, float* __restrict__ out) {
    int idx = blockIdx.x * blockDim.x + threadIdx.x;   // 262144
    float4 v = ((const float4*)F)[idx];
    ((__nv_bfloat162*)g_fb)[idx * 2]     = __floats2bfloat162_rn(v.x, v.y);
    ((__nv_bfloat162*)g_fb)[idx * 2 + 1] = __floats2bfloat162_rn(v.z, v.w);
    if (idx < BATCH) {
        g_min_enc[idx] = 0xFFFFFFFFu;
        g_max_enc[idx] = 0u;
        g_possum[idx] = 0.0f;
        g_negsum[idx] = 0.0f;
    }
    if (idx == 0) out[0] = 0.0f;
}

template <int PASS>
__global__ __launch_bounds__(THREADS, 1)
void ms_tri(const int* __restrict__ L) {
    extern __shared__ char smem[];
    const uint32_t sb = smem_to_u32(smem);
    const int tid = threadIdx.x;
    const int lane = tid & 31;
    const int w = tid >> 5;
    const int wm = w >> 2, wn = w & 3;   // warp tile: rows wm*64+, cols wn*32+

    // static per-thread ldsm geometry
    uint32_t aRow[4], aSw[4], bRow[2], bSw[2];
    const int khA = lane >> 4;
    const int khB = (lane >> 3) & 1;
#pragma unroll
    for (int mt = 0; mt < 4; mt++) {
        int r = wm * 64 + mt * 16 + (lane & 15);
        aRow[mt] = r * 256;
        aSw[mt] = r & 7;
    }
#pragma unroll
    for (int p = 0; p < 2; p++) {
        int r = wn * 32 + p * 16 + ((lane >> 4) << 3) + (lane & 7);
        bRow[p] = r * 256;
        bSw[p] = r & 7;
    }
    int rowL[8], colL[8];
#pragma unroll
    for (int i = 0; i < 8; i++)
        rowL[i] = wm * 64 + (i >> 1) * 16 + (lane >> 2) + (i & 1) * 8;
#pragma unroll
    for (int cj = 0; cj < 8; cj++)
        colL[cj] = wn * 32 + (cj >> 1) * 8 + 2 * (lane & 3) + (cj & 1);

    // prologue: prefetch first tile pair
    {
        int ti, tj;
        decode_tile(blockIdx.x, ti, tj);
        prefetch_pair(ti, tj, 0, sb, L, tid);
    }
    CP_COMMIT();

    int it = 0;
    for (int tile = blockIdx.x; tile < NTILES_TRI; tile += GRID_MAIN, it++) {
        const int buf = it & 1;
        int ti, tj;
        decode_tile(tile, ti, tj);
        const int rowBase = ti * 128, colBase = tj * 128;
        const bool diag = (ti == tj);

        CP_WAIT0();
        __syncthreads();   // tile data visible; prev iter fully done

        if (tile + GRID_MAIN < NTILES_TRI) {
            int ti2, tj2;
            decode_tile(tile + GRID_MAIN, ti2, tj2);
            prefetch_pair(ti2, tj2, buf ^ 1, sb, L, tid);
        }
        CP_COMMIT();

        if (PASS == 1) {   // per-tile thresholds into smem
            if (tid < 128) {
                float mn = dec_f(g_min_enc[rowBase + tid]);
                float mx = dec_f(g_max_enc[rowBase + tid]);
                ((float*)(smem + OFF_TPR))[tid] = fminf(ONE_M_EPS, mx + MARGIN_F);
                ((float*)(smem + OFF_TNR))[tid] = mn - MARGIN_F;
            } else {
                int c = tid - 128;
                float mn = dec_f(g_min_enc[colBase + c]);
                float mx = dec_f(g_max_enc[colBase + c]);
                ((float*)(smem + OFF_TPC))[c] = fminf(ONE_M_EPS, mx + MARGIN_F);
                ((float*)(smem + OFF_TNC))[c] = mn - MARGIN_F;
            }
        }

        // ---- GEMM 128x128x128 ----
        const uint32_t aBase = sb + (buf ? OFF_A1 : OFF_A0);
        const uint32_t bBase = sb + (buf ? OFF_B1 : OFF_B0);
        float d[4][4][4];
#pragma unroll
        for (int mt = 0; mt < 4; mt++)
#pragma unroll
            for (int nt = 0; nt < 4; nt++)
#pragma unroll
                for (int r = 0; r < 4; r++) d[mt][nt][r] = 0.0f;
#pragma unroll
        for (int ks = 0; ks < 8; ks++) {
            uint32_t a[4][4], bb[2][4];
#pragma unroll
            for (int mt = 0; mt < 4; mt++)
                ldsm_x4(a[mt], aBase + aRow[mt] + (((2 * ks + khA) ^ aSw[mt]) << 4));
#pragma unroll
            for (int p = 0; p < 2; p++)
                ldsm_x4(bb[p], bBase + bRow[p] + (((2 * ks + khB) ^ bSw[p]) << 4));
#pragma unroll
            for (int mt = 0; mt < 4; mt++)
#pragma unroll
                for (int nt = 0; nt < 4; nt++)
                    mma_bf16(d[mt][nt], a[mt], bb[nt >> 1][(nt & 1) * 2],
                             bb[nt >> 1][(nt & 1) * 2 + 1]);
        }
        __syncthreads();   // thresholds (PASS1) visible to all

        // ---- epilogue ----
        const int* labA = (const int*)(smem + OFF_LABA + buf * 512);
        const int* labB = (const int*)(smem + OFF_LABB + buf * 512);
        float s0r[8], s1r[8], s0c[8], s1c[8];
        float pR[8], nR[8], pC[8], nC[8];
        int rl[8], cl[8];
#pragma unroll
        for (int i = 0; i < 8; i++) {
            rl[i] = labA[rowL[i]];
            cl[i] = labB[colL[i]];
            if (PASS == 0) {
                s0r[i] = inf_f(); s1r[i] = -inf_f();
                s0c[i] = inf_f(); s1c[i] = -inf_f();
            } else {
                s0r[i] = 0.0f; s1r[i] = 0.0f; s0c[i] = 0.0f; s1c[i] = 0.0f;
                pR[i] = ((const float*)(smem + OFF_TPR))[rowL[i]];
                nR[i] = ((const float*)(smem + OFF_TNR))[rowL[i]];
                pC[i] = ((const float*)(smem + OFF_TPC))[colL[i]];
                nC[i] = ((const float*)(smem + OFF_TNC))[colL[i]];
            }
        }

#pragma unroll
        for (int mt = 0; mt < 4; mt++)
#pragma unroll
            for (int nt = 0; nt < 4; nt++)
#pragma unroll
                for (int rix = 0; rix < 4; rix++) {
                    const int i = mt * 2 + (rix >> 1);
                    const int cj = nt * 2 + (rix & 1);
                    const float sim = d[mt][nt][rix];
                    const bool same = (rl[i] == cl[cj]);
                    const bool self = diag && (rowL[i] == colL[cj]);
                    if (PASS == 0) {
                        if (same) {
                            if (sim < ONE_M_EPS && !self) {
                                s0r[i] = fminf(s0r[i], sim);
                                s0c[cj] = fminf(s0c[cj], sim);
                            }
                        } else {
                            s1r[i] = fmaxf(s1r[i], sim);
                            s1c[cj] = fmaxf(s1c[cj], sim);
                        }
                    } else {
                        const float e = ex2f(fmaf(sim, same ? A_POS : A_NEG,
                                                  same ? B_POS : B_NEG));
                        if (same) {
                            if (!self) {
                                if (sim < pR[i]) s0r[i] += e;
                                if (sim < pC[cj]) s0c[cj] += e;
                            }
                        } else {
                            if (sim > nR[i]) s1r[i] += e;
                            if (sim > nC[cj]) s1c[cj] += e;
                        }
                    }
                }

        // ---- reductions + atomics ----
        float* rr0 = (float*)(smem + OFF_RR0);
        float* rr1 = (float*)(smem + OFF_RR1);
        float* rc0 = (float*)(smem + OFF_RC0);
        float* rc1 = (float*)(smem + OFF_RC1);
#pragma unroll
        for (int i = 0; i < 8; i++) {   // rows: reduce over 4 col-lanes
            float v0 = s0r[i], v1 = s1r[i];
#pragma unroll
            for (int m = 1; m <= 2; m <<= 1) {
                float o0 = __shfl_xor_sync(0xffffffff, v0, m);
                float o1 = __shfl_xor_sync(0xffffffff, v1, m);
                if (PASS == 0) { v0 = fminf(v0, o0); v1 = fmaxf(v1, o1); }
                else           { v0 += o0; v1 += o1; }
            }
            if ((lane & 3) == 0) {
                rr0[wn * 128 + rowL[i]] = v0;
                rr1[wn * 128 + rowL[i]] = v1;
            }
        }
#pragma unroll
        for (int cj = 0; cj < 8; cj++) {   // cols: reduce over 8 row-lane-groups
            float v0 = s0c[cj], v1 = s1c[cj];
#pragma unroll
            for (int m = 4; m <= 16; m <<= 1) {
                float o0 = __shfl_xor_sync(0xffffffff, v0, m);
                float o1 = __shfl_xor_sync(0xffffffff, v1, m);
                if (PASS == 0) { v0 = fminf(v0, o0); v1 = fmaxf(v1, o1); }
                else           { v0 += o0; v1 += o1; }
            }
            if (lane < 4) {
                rc0[wm * 128 + colL[cj]] = v0;
                rc1[wm * 128 + colL[cj]] = v1;
            }
        }
        __syncthreads();

        if (tid < 128) {
            if (PASS == 0) {
                float mn = fminf(fminf(rr0[tid], rr0[128 + tid]),
                                 fminf(rr0[256 + tid], rr0[384 + tid]));
                float mx = fmaxf(fmaxf(rr1[tid], rr1[128 + tid]),
                                 fmaxf(rr1[256 + tid], rr1[384 + tid]));
                atomicMin(&g_min_enc[rowBase + tid], enc_f(mn));
                atomicMax(&g_max_enc[rowBase + tid], enc_f(mx));
            } else {
                float ps = rr0[tid] + rr0[128 + tid] + rr0[256 + tid] + rr0[384 + tid];
                float ns = rr1[tid] + rr1[128 + tid] + rr1[256 + tid] + rr1[384 + tid];
                atomicAdd(&g_possum[rowBase + tid], ps);
                atomicAdd(&g_negsum[rowBase + tid], ns);
            }
        } else if (!diag) {
            int c = tid - 128;
            if (PASS == 0) {
                float mn = fminf(rc0[c], rc0[128 + c]);
                float mx = fmaxf(rc1[c], rc1[128 + c]);
                atomicMin(&g_min_enc[colBase + c], enc_f(mn));
                atomicMax(&g_max_enc[colBase + c], enc_f(mx));
            } else {
                atomicAdd(&g_possum[colBase + c], rc0[c] + rc0[128 + c]);
                atomicAdd(&g_negsum[colBase + c], rc1[c] + rc1[128 + c]);
            }
        }
    }
}

__global__ void ms_final(float* __restrict__ out) {
    __shared__ float red[4];
    int r = blockIdx.x * 128 + threadIdx.x;
    float mn = dec_f(g_min_enc[r]);
    float mx = dec_f(g_max_enc[r]);
    float local = 0.0f;
    if (mn < inf_f() && mx > -inf_f() && (mn - MARGIN_F < mx))
        local = 0.5f * log1pf(g_possum[r]) + 0.025f * log1pf(g_negsum[r]);
#pragma unroll
    for (int m = 16; m > 0; m >>= 1)
        local += __shfl_xor_sync(0xffffffff, local, m);
    if ((threadIdx.x & 31) == 0) red[threadIdx.x >> 5] = local;
    __syncthreads();
    if (threadIdx.x == 0)
        atomicAdd(out, red[0] + red[1] + red[2] + red[3]);
}

extern "C" void kernel_launch(void* const* d_in, const int* in_sizes, int n_in,
                              void* d_out, int out_size) {
    const float* F = (const float*)d_in[0];
    const int* L = (const int*)d_in[1];
    if (n_in >= 2 && in_sizes[0] == BATCH) {  // defensive: inputs swapped
        F = (const float*)d_in[1];
        L = (const int*)d_in[0];
    }

    cudaFuncSetAttribute(ms_tri<0>, cudaFuncAttributeMaxDynamicSharedMemorySize, SMEM_BYTES);
    cudaFuncSetAttribute(ms_tri<1>, cudaFuncAttributeMaxDynamicSharedMemorySize, SMEM_BYTES);

    prep_k<<<1024, 256>>>(F, (float*)d_out);
    ms_tri<0><<<GRID_MAIN, THREADS, SMEM_BYTES>>>(L);
    ms_tri<1><<<GRID_MAIN, THREADS, SMEM_BYTES>>>(L);
    ms_final<<<BATCH / 128, 128>>>((float*)d_out);
}

// round 5
// speedup vs baseline: 8.0648x; 1.2189x over previous
#include <cuda_runtime.h>
#include <cuda_bf16.h>
#include <math.h>
#include <cstdint>

#define BATCH 8192
#define DIM   128
#define NTILES_TRI 2080          // 64*65/2 triangle tiles of 128x128
#define GRID_MAIN 148
#define THREADS 512

#define MARGIN_F 0.1f
#define ONE_M_EPS 0.99999f
#define LOG2E 1.44269504089f
// arg = scale*(sim-0.5)*log2e -> sim*A + B
#define A_POS (-2.0f * LOG2E)
#define B_POS (LOG2E)
#define A_NEG (40.0f * LOG2E)
#define B_NEG (-20.0f * LOG2E)

__device__ __nv_bfloat16 g_fb[BATCH * DIM];
__device__ unsigned int g_min_enc[BATCH];
__device__ unsigned int g_max_enc[BATCH];
__device__ float g_possum[BATCH];
__device__ float g_negsum[BATCH];

__device__ __forceinline__ float inf_f() { return __int_as_float(0x7f800000); }
__device__ __forceinline__ unsigned enc_f(float x) {
    unsigned u = __float_as_uint(x);
    return (u & 0x80000000u) ? ~u : (u | 0x80000000u);
}
__device__ __forceinline__ float dec_f(unsigned e) {
    return __uint_as_float((e & 0x80000000u) ? (e & 0x7FFFFFFFu) : ~e);
}
__device__ __forceinline__ float ex2f(float x) {
    float r;
    asm("ex2.approx.f32 %0, %1;" : "=f"(r) : "f"(x));
    return r;
}
__device__ __forceinline__ uint32_t smem_to_u32(const void* p) {
    uint32_t a;
    asm("{ .reg .u64 t; cvta.to.shared.u64 t, %1; cvt.u32.u64 %0, t; }"
        : "=r"(a) : "l"(p));
    return a;
}
__device__ __forceinline__ void ldsm_x4(uint32_t (&r)[4], uint32_t addr) {
    asm volatile("ldmatrix.sync.aligned.m8n8.x4.shared.b16 {%0,%1,%2,%3}, [%4];"
                 : "=r"(r[0]), "=r"(r[1]), "=r"(r[2]), "=r"(r[3]) : "r"(addr));
}
__device__ __forceinline__ void mma_bf16(float (&d)[4], const uint32_t (&a)[4],
                                         uint32_t b0, uint32_t b1) {
    asm volatile("mma.sync.aligned.m16n8k16.row.col.f32.bf16.bf16.f32 "
                 "{%0,%1,%2,%3}, {%4,%5,%6,%7}, {%8,%9}, {%0,%1,%2,%3};"
                 : "+f"(d[0]), "+f"(d[1]), "+f"(d[2]), "+f"(d[3])
                 : "r"(a[0]), "r"(a[1]), "r"(a[2]), "r"(a[3]), "r"(b0), "r"(b1));
}
#define CP_ASYNC16(sa, g) \
    asm volatile("cp.async.cg.shared.global [%0], [%1], 16;" :: "r"(sa), "l"(g) : "memory")
#define CP_COMMIT() asm volatile("cp.async.commit_group;" ::: "memory")
#define CP_WAIT0()  asm volatile("cp.async.wait_group 0;" ::: "memory")

// ---- smem layout (bytes) ----
#define OFF_A0   0
#define OFF_A1   32768
#define OFF_B0   65536
#define OFF_B1   98304
#define OFF_LABA 131072      // [2][128] int
#define OFF_LABB 132096      // [2][128] int
#define OFF_TPR  133120      // float[128] each
#define OFF_TNR  133632
#define OFF_TPC  134144
#define OFF_TNC  134656
#define OFF_RR0  135168      // float[4][128]
#define OFF_RR1  137216
#define OFF_RC0  139264      // float[4][128]
#define OFF_RC1  141312
#define SMEM_BYTES 143360

// 128x128 bf16 tile -> smem, 256B rows, 16B chunks XOR-swizzled by (row&7)
__device__ __forceinline__ void prefetch_tile(const __nv_bfloat16* src,
                                              uint32_t dstBase, int tid) {
#pragma unroll
    for (int i = 0; i < 4; i++) {
        int idx = tid + i * THREADS;   // 0..2047
        int r = idx >> 4, c = idx & 15;
        uint32_t sa = dstBase + r * 256 + ((c ^ (r & 7)) << 4);
        CP_ASYNC16(sa, (const char*)src + r * 256 + c * 16);
    }
}

__device__ __forceinline__ void decode_tile(int k, int& ti, int& tj) {
    int a = (int)((sqrtf(8.0f * (float)k + 1.0f) - 1.0f) * 0.5f);
    while ((a + 1) * (a + 2) / 2 <= k) ++a;
    while (a * (a + 1) / 2 > k) --a;
    tj = a;
    ti = k - a * (a + 1) / 2;   // ti <= tj
}

__device__ __forceinline__ void prefetch_pair(int ti, int tj, int buf,
                                              uint32_t sb, const int* L, int tid) {
    prefetch_tile(g_fb + (size_t)ti * 128 * DIM, sb + (buf ? OFF_A1 : OFF_A0), tid);
    prefetch_tile(g_fb + (size_t)tj * 128 * DIM, sb + (buf ? OFF_B1 : OFF_B0), tid);
    if (tid < 32)
        CP_ASYNC16(sb + OFF_LABA + buf * 512 + tid * 16, L + ti * 128 + tid * 4);
    else if (tid < 64)
        CP_ASYNC16(sb + OFF_LABB + buf * 512 + (tid - 32) * 16, L + tj * 128 + (tid - 32) * 4);
}

__global__ void prep_k(const float* __restrict__ F, float* __restrict__ out) {
    int idx = blockIdx.x * blockDim.x + threadIdx.x;   // 262144
    float4 v = ((const float4*)F)[idx];
    ((__nv_bfloat162*)g_fb)[idx * 2]     = __floats2bfloat162_rn(v.x, v.y);
    ((__nv_bfloat162*)g_fb)[idx * 2 + 1] = __floats2bfloat162_rn(v.z, v.w);
    if (idx < BATCH) {
        g_min_enc[idx] = 0xFFFFFFFFu;
        g_max_enc[idx] = 0u;
        g_possum[idx] = 0.0f;
        g_negsum[idx] = 0.0f;
    }
    if (idx == 0) out[0] = 0.0f;
}

// epilogue over one warp's 32x32 fragment
template <int PASS, bool DIAG>
__device__ __forceinline__ void epilogue_frag(
    const float (&d)[2][4][4], const int (&rl)[4], const int (&cl)[8],
    const int (&rowL)[4], const int (&colL)[8],
    const float* tpr, const float* tnr, const float* tpc, const float* tnc,
    float (&s0r)[4], float (&s1r)[4], float (&s0c)[8], float (&s1c)[8]) {
    float pR[4], nR[4], pC[8], nC[8];
    if (PASS == 1) {
#pragma unroll
        for (int i = 0; i < 4; i++) { pR[i] = tpr[rowL[i]]; nR[i] = tnr[rowL[i]]; }
#pragma unroll
        for (int j = 0; j < 8; j++) { pC[j] = tpc[colL[j]]; nC[j] = tnc[colL[j]]; }
    }
#pragma unroll
    for (int mt = 0; mt < 2; mt++)
#pragma unroll
        for (int nt = 0; nt < 4; nt++)
#pragma unroll
            for (int rix = 0; rix < 4; rix++) {
                const int i = mt * 2 + (rix >> 1);
                const int cj = nt * 2 + (rix & 1);
                const float sim = d[mt][nt][rix];
                const bool same = (rl[i] == cl[cj]);
                const bool self = DIAG && (rowL[i] == colL[cj]);
                if (PASS == 0) {
                    if (same) {
                        if (sim < ONE_M_EPS && !self) {
                            s0r[i] = fminf(s0r[i], sim);
                            s0c[cj] = fminf(s0c[cj], sim);
                        }
                    } else {
                        s1r[i] = fmaxf(s1r[i], sim);
                        s1c[cj] = fmaxf(s1c[cj], sim);
                    }
                } else {
                    const float e = ex2f(fmaf(sim, same ? A_POS : A_NEG,
                                              same ? B_POS : B_NEG));
                    if (same) {
                        if (!self) {
                            if (sim < pR[i]) s0r[i] += e;
                            if (sim < pC[cj]) s0c[cj] += e;
                        }
                    } else {
                        if (sim > nR[i]) s1r[i] += e;
                        if (sim > nC[cj]) s1c[cj] += e;
                    }
                }
            }
}

template <int PASS>
__global__ __launch_bounds__(THREADS, 1)
void ms_tri(const int* __restrict__ L) {
    extern __shared__ char smem[];
    const uint32_t sb = smem_to_u32(smem);
    const int tid = threadIdx.x;
    const int lane = tid & 31;
    const int w = tid >> 5;              // 0..15
    const int wm = w >> 2, wn = w & 3;   // 4x4 warp grid, 32x32 warp tile

    // static per-warp ldsm geometry
    uint32_t aRow[2], aSw[2], bRow[2], bSw[2];
    const int khA = lane >> 4;
    const int khB = (lane >> 3) & 1;
#pragma unroll
    for (int mt = 0; mt < 2; mt++) {
        int r = wm * 32 + mt * 16 + (lane & 15);
        aRow[mt] = r * 256;
        aSw[mt] = r & 7;
    }
#pragma unroll
    for (int p = 0; p < 2; p++) {
        int r = wn * 32 + p * 16 + ((lane >> 4) << 3) + (lane & 7);
        bRow[p] = r * 256;
        bSw[p] = r & 7;
    }
    int rowL[4], colL[8];
#pragma unroll
    for (int i = 0; i < 4; i++)
        rowL[i] = wm * 32 + (i >> 1) * 16 + (lane >> 2) + (i & 1) * 8;
#pragma unroll
    for (int cj = 0; cj < 8; cj++)
        colL[cj] = wn * 32 + (cj >> 1) * 8 + 2 * (lane & 3) + (cj & 1);

    const float* tpr = (const float*)(smem + OFF_TPR);
    const float* tnr = (const float*)(smem + OFF_TNR);
    const float* tpc = (const float*)(smem + OFF_TPC);
    const float* tnc = (const float*)(smem + OFF_TNC);

    {   // prologue prefetch
        int ti, tj;
        decode_tile(blockIdx.x, ti, tj);
        prefetch_pair(ti, tj, 0, sb, L, tid);
    }
    CP_COMMIT();

    int it = 0;
    for (int tile = blockIdx.x; tile < NTILES_TRI; tile += GRID_MAIN, it++) {
        const int buf = it & 1;
        int ti, tj;
        decode_tile(tile, ti, tj);
        const int rowBase = ti * 128, colBase = tj * 128;
        const bool diag = (ti == tj);

        CP_WAIT0();
        __syncthreads();   // tile data visible; reduction arrays free

        if (tile + GRID_MAIN < NTILES_TRI) {
            int ti2, tj2;
            decode_tile(tile + GRID_MAIN, ti2, tj2);
            prefetch_pair(ti2, tj2, buf ^ 1, sb, L, tid);
        }
        CP_COMMIT();

        if (PASS == 1) {   // per-tile thresholds into smem
            if (tid < 128) {
                float mn = dec_f(g_min_enc[rowBase + tid]);
                float mx = dec_f(g_max_enc[rowBase + tid]);
                ((float*)(smem + OFF_TPR))[tid] = fminf(ONE_M_EPS, mx + MARGIN_F);
                ((float*)(smem + OFF_TNR))[tid] = mn - MARGIN_F;
            } else if (tid < 256) {
                int c = tid - 128;
                float mn = dec_f(g_min_enc[colBase + c]);
                float mx = dec_f(g_max_enc[colBase + c]);
                ((float*)(smem + OFF_TPC))[c] = fminf(ONE_M_EPS, mx + MARGIN_F);
                ((float*)(smem + OFF_TNC))[c] = mn - MARGIN_F;
            }
        }

        // ---- GEMM 128x128x128 (warp: 32x32) ----
        const uint32_t aBase = sb + (buf ? OFF_A1 : OFF_A0);
        const uint32_t bBase = sb + (buf ? OFF_B1 : OFF_B0);
        float d[2][4][4];
#pragma unroll
        for (int mt = 0; mt < 2; mt++)
#pragma unroll
            for (int nt = 0; nt < 4; nt++)
#pragma unroll
                for (int r = 0; r < 4; r++) d[mt][nt][r] = 0.0f;
#pragma unroll
        for (int ks = 0; ks < 8; ks++) {
            uint32_t a[2][4], bb[2][4];
#pragma unroll
            for (int mt = 0; mt < 2; mt++)
                ldsm_x4(a[mt], aBase + aRow[mt] + (((2 * ks + khA) ^ aSw[mt]) << 4));
#pragma unroll
            for (int p = 0; p < 2; p++)
                ldsm_x4(bb[p], bBase + bRow[p] + (((2 * ks + khB) ^ bSw[p]) << 4));
#pragma unroll
            for (int mt = 0; mt < 2; mt++)
#pragma unroll
                for (int nt = 0; nt < 4; nt++)
                    mma_bf16(d[mt][nt], a[mt], bb[nt >> 1][(nt & 1) * 2],
                             bb[nt >> 1][(nt & 1) * 2 + 1]);
        }
        if (PASS == 1) __syncthreads();   // thresholds visible

        // ---- epilogue ----
        const int* labA = (const int*)(smem + OFF_LABA + buf * 512);
        const int* labB = (const int*)(smem + OFF_LABB + buf * 512);
        int rl[4], cl[8];
        float s0r[4], s1r[4], s0c[8], s1c[8];
#pragma unroll
        for (int i = 0; i < 4; i++) {
            rl[i] = labA[rowL[i]];
            s0r[i] = (PASS == 0) ? inf_f() : 0.0f;
            s1r[i] = (PASS == 0) ? -inf_f() : 0.0f;
        }
#pragma unroll
        for (int j = 0; j < 8; j++) {
            cl[j] = labB[colL[j]];
            s0c[j] = (PASS == 0) ? inf_f() : 0.0f;
            s1c[j] = (PASS == 0) ? -inf_f() : 0.0f;
        }
        if (diag)
            epilogue_frag<PASS, true>(d, rl, cl, rowL, colL, tpr, tnr, tpc, tnc,
                                      s0r, s1r, s0c, s1c);
        else
            epilogue_frag<PASS, false>(d, rl, cl, rowL, colL, tpr, tnr, tpc, tnc,
                                       s0r, s1r, s0c, s1c);

        // ---- reductions ----
        float* rr0 = (float*)(smem + OFF_RR0);
        float* rr1 = (float*)(smem + OFF_RR1);
        float* rc0 = (float*)(smem + OFF_RC0);
        float* rc1 = (float*)(smem + OFF_RC1);
#pragma unroll
        for (int i = 0; i < 4; i++) {   // rows: reduce over 4 col-lanes
            float v0 = s0r[i], v1 = s1r[i];
#pragma unroll
            for (int m = 1; m <= 2; m <<= 1) {
                float o0 = __shfl_xor_sync(0xffffffff, v0, m);
                float o1 = __shfl_xor_sync(0xffffffff, v1, m);
                if (PASS == 0) { v0 = fminf(v0, o0); v1 = fmaxf(v1, o1); }
                else           { v0 += o0; v1 += o1; }
            }
            if ((lane & 3) == 0) {
                rr0[wn * 128 + rowL[i]] = v0;
                rr1[wn * 128 + rowL[i]] = v1;
            }
        }
#pragma unroll
        for (int cj = 0; cj < 8; cj++) {   // cols: reduce over 8 row-lane-groups
            float v0 = s0c[cj], v1 = s1c[cj];
#pragma unroll
            for (int m = 4; m <= 16; m <<= 1) {
                float o0 = __shfl_xor_sync(0xffffffff, v0, m);
                float o1 = __shfl_xor_sync(0xffffffff, v1, m);
                if (PASS == 0) { v0 = fminf(v0, o0); v1 = fmaxf(v1, o1); }
                else           { v0 += o0; v1 += o1; }
            }
            if (lane < 4) {
                rc0[wm * 128 + colL[cj]] = v0;
                rc1[wm * 128 + colL[cj]] = v1;
            }
        }
        __syncthreads();

        if (tid < 128) {
            if (PASS == 0) {
                float mn = fminf(fminf(rr0[tid], rr0[128 + tid]),
                                 fminf(rr0[256 + tid], rr0[384 + tid]));
                float mx = fmaxf(fmaxf(rr1[tid], rr1[128 + tid]),
                                 fmaxf(rr1[256 + tid], rr1[384 + tid]));
                atomicMin(&g_min_enc[rowBase + tid], enc_f(mn));
                atomicMax(&g_max_enc[rowBase + tid], enc_f(mx));
            } else {
                atomicAdd(&g_possum[rowBase + tid],
                          rr0[tid] + rr0[128 + tid] + rr0[256 + tid] + rr0[384 + tid]);
                atomicAdd(&g_negsum[rowBase + tid],
                          rr1[tid] + rr1[128 + tid] + rr1[256 + tid] + rr1[384 + tid]);
            }
        } else if (tid < 256 && !diag) {
            int c = tid - 128;
            if (PASS == 0) {
                float mn = fminf(fminf(rc0[c], rc0[128 + c]),
                                 fminf(rc0[256 + c], rc0[384 + c]));
                float mx = fmaxf(fmaxf(rc1[c], rc1[128 + c]),
                                 fmaxf(rc1[256 + c], rc1[384 + c]));
                atomicMin(&g_min_enc[colBase + c], enc_f(mn));
                atomicMax(&g_max_enc[colBase + c], enc_f(mx));
            } else {
                atomicAdd(&g_possum[colBase + c],
                          rc0[c] + rc0[128 + c] + rc0[256 + c] + rc0[384 + c]);
                atomicAdd(&g_negsum[colBase + c],
                          rc1[c] + rc1[128 + c] + rc1[256 + c] + rc1[384 + c]);
            }
        }
    }
}

__global__ void ms_final(float* __restrict__ out) {
    __shared__ float red[4];
    int r = blockIdx.x * 128 + threadIdx.x;
    float mn = dec_f(g_min_enc[r]);
    float mx = dec_f(g_max_enc[r]);
    float local = 0.0f;
    if (mn < inf_f() && mx > -inf_f() && (mn - MARGIN_F < mx))
        local = 0.5f * log1pf(g_possum[r]) + 0.025f * log1pf(g_negsum[r]);
#pragma unroll
    for (int m = 16; m > 0; m >>= 1)
        local += __shfl_xor_sync(0xffffffff, local, m);
    if ((threadIdx.x & 31) == 0) red[threadIdx.x >> 5] = local;
    __syncthreads();
    if (threadIdx.x == 0)
        atomicAdd(out, red[0] + red[1] + red[2] + red[3]);
}

extern "C" void kernel_launch(void* const* d_in, const int* in_sizes, int n_in,
                              void* d_out, int out_size) {
    const float* F = (const float*)d_in[0];
    const int* L = (const int*)d_in[1];
    if (n_in >= 2 && in_sizes[0] == BATCH) {  // defensive: inputs swapped
        F = (const float*)d_in[1];
        L = (const int*)d_in[0];
    }

    cudaFuncSetAttribute(ms_tri<0>, cudaFuncAttributeMaxDynamicSharedMemorySize, SMEM_BYTES);
    cudaFuncSetAttribute(ms_tri<1>, cudaFuncAttributeMaxDynamicSharedMemorySize, SMEM_BYTES);

    prep_k<<<1024, 256>>>(F, (float*)d_out);
    ms_tri<0><<<GRID_MAIN, THREADS, SMEM_BYTES>>>(L);
    ms_tri<1><<<GRID_MAIN, THREADS, SMEM_BYTES>>>(L);
    ms_final<<<BATCH / 128, 128>>>((float*)d_out);
}

// round 6
// speedup vs baseline: 8.2663x; 1.0250x over previous
#include <cuda_runtime.h>
#include <cuda_bf16.h>
#include <math.h>
#include <cstdint>

#define BATCH 8192
#define DIM   128
#define NSUPER 528               // 32*33/2 supertiles of 256x256
#define GRID_MAIN 148
#define THREADS 512

#define MARGIN_F 0.1f
#define ONE_M_EPS 0.99999f
#define LOG2E 1.44269504089f
// arg = scale*(sim-0.5)*log2e -> sim*A + B
#define A_POS (-2.0f * LOG2E)
#define B_POS (LOG2E)
#define A_NEG (40.0f * LOG2E)
#define B_NEG (-20.0f * LOG2E)

__device__ __nv_bfloat16 g_fb[BATCH * DIM];
__device__ unsigned int g_min_enc[BATCH];
__device__ unsigned int g_max_enc[BATCH];
__device__ float g_possum[BATCH];
__device__ float g_negsum[BATCH];
__device__ unsigned int g_done;

__device__ __forceinline__ float inf_f() { return __int_as_float(0x7f800000); }
__device__ __forceinline__ unsigned enc_f(float x) {
    unsigned u = __float_as_uint(x);
    return (u & 0x80000000u) ? ~u : (u | 0x80000000u);
}
__device__ __forceinline__ float dec_f(unsigned e) {
    return __uint_as_float((e & 0x80000000u) ? (e & 0x7FFFFFFFu) : ~e);
}
__device__ __forceinline__ float ex2f(float x) {
    float r;
    asm("ex2.approx.f32 %0, %1;" : "=f"(r) : "f"(x));
    return r;
}
__device__ __forceinline__ uint32_t smem_to_u32(const void* p) {
    uint32_t a;
    asm("{ .reg .u64 t; cvta.to.shared.u64 t, %1; cvt.u32.u64 %0, t; }"
        : "=r"(a) : "l"(p));
    return a;
}
__device__ __forceinline__ void ldsm_x4(uint32_t (&r)[4], uint32_t addr) {
    asm volatile("ldmatrix.sync.aligned.m8n8.x4.shared.b16 {%0,%1,%2,%3}, [%4];"
                 : "=r"(r[0]), "=r"(r[1]), "=r"(r[2]), "=r"(r[3]) : "r"(addr));
}
__device__ __forceinline__ void mma_bf16(float (&d)[4], const uint32_t (&a)[4],
                                         uint32_t b0, uint32_t b1) {
    asm volatile("mma.sync.aligned.m16n8k16.row.col.f32.bf16.bf16.f32 "
                 "{%0,%1,%2,%3}, {%4,%5,%6,%7}, {%8,%9}, {%0,%1,%2,%3};"
                 : "+f"(d[0]), "+f"(d[1]), "+f"(d[2]), "+f"(d[3])
                 : "r"(a[0]), "r"(a[1]), "r"(a[2]), "r"(a[3]), "r"(b0), "r"(b1));
}
#define CP_ASYNC16(sa, g) \
    asm volatile("cp.async.cg.shared.global [%0], [%1], 16;" :: "r"(sa), "l"(g) : "memory")
#define CP_COMMIT() asm volatile("cp.async.commit_group;" ::: "memory")
#define CP_WAIT0()  asm volatile("cp.async.wait_group 0;" ::: "memory")

// ---- smem layout (bytes) ----
#define OFF_A    0           // 2 panels x 32KB
#define OFF_B    65536       // 2 panels x 32KB
#define OFF_LABA 131072      // int[256]
#define OFF_LABB 132096      // int[256]
#define OFF_TPR  133120      // float[256] each
#define OFF_TNR  134144
#define OFF_TPC  135168
#define OFF_TNC  136192
#define OFF_RR0  137216      // float[2][4][128] each (4KB)
#define OFF_RR1  141312
#define OFF_RC0  145408
#define OFF_RC1  149504
#define SMEM_BYTES 153600

__device__ __forceinline__ void decode_st(int k, int& ti, int& tj) {
    int a = (int)((sqrtf(8.0f * (float)k + 1.0f) - 1.0f) * 0.5f);
    while ((a + 1) * (a + 2) / 2 <= k) ++a;
    while (a * (a + 1) / 2 > k) --a;
    tj = a;
    ti = k - a * (a + 1) / 2;   // ti <= tj
}

// prefetch one 256x256 supertile: A rows [I*256,+256), B rows [J*256,+256)
// 256B rows, 16B chunks XOR-swizzled by (row&7). Skips B when I==J.
__device__ __forceinline__ void prefetch_super(int I, int J, uint32_t sb,
                                               const int* L, int tid) {
    const char* srcA = (const char*)(g_fb + (size_t)I * 256 * DIM);
#pragma unroll
    for (int i = 0; i < 8; i++) {
        int idx = tid + i * THREADS;   // 0..4095
        int r = idx >> 4, c = idx & 15;
        CP_ASYNC16(sb + OFF_A + r * 256 + ((c ^ (r & 7)) << 4), srcA + r * 256 + c * 16);
    }
    if (I != J) {
        const char* srcB = (const char*)(g_fb + (size_t)J * 256 * DIM);
#pragma unroll
        for (int i = 0; i < 8; i++) {
            int idx = tid + i * THREADS;
            int r = idx >> 4, c = idx & 15;
            CP_ASYNC16(sb + OFF_B + r * 256 + ((c ^ (r & 7)) << 4), srcB + r * 256 + c * 16);
        }
    }
    if (tid < 64)
        CP_ASYNC16(sb + OFF_LABA + tid * 16, L + I * 256 + tid * 4);
    else if (tid < 128 && I != J)
        CP_ASYNC16(sb + OFF_LABB + (tid - 64) * 16, L + J * 256 + (tid - 64) * 4);
}

__global__ void prep_k(const float* __restrict__ F, float* __restrict__ out) {
    int idx = blockIdx.x * blockDim.x + threadIdx.x;   // 262144
    float4 v = ((const float4*)F)[idx];
    ((__nv_bfloat162*)g_fb)[idx * 2]     = __floats2bfloat162_rn(v.x, v.y);
    ((__nv_bfloat162*)g_fb)[idx * 2 + 1] = __floats2bfloat162_rn(v.z, v.w);
    if (idx < BATCH) {
        g_min_enc[idx] = 0xFFFFFFFFu;
        g_max_enc[idx] = 0u;
        g_possum[idx] = 0.0f;
        g_negsum[idx] = 0.0f;
    }
    if (idx == 0) { g_done = 0u; out[0] = 0.0f; }
}

// one 128x128 subtile GEMM, warp computes 32x32
__device__ __forceinline__ void gemm_sub(uint32_t aBase, uint32_t bBase,
                                         const uint32_t (&aRow)[2], const uint32_t (&aSw)[2],
                                         const uint32_t (&bRow)[2], const uint32_t (&bSw)[2],
                                         int khA, int khB, float (&d)[2][4][4]) {
#pragma unroll
    for (int mt = 0; mt < 2; mt++)
#pragma unroll
        for (int nt = 0; nt < 4; nt++)
#pragma unroll
            for (int r = 0; r < 4; r++) d[mt][nt][r] = 0.0f;
#pragma unroll
    for (int ks = 0; ks < 8; ks++) {
        uint32_t a[2][4], bb[2][4];
#pragma unroll
        for (int mt = 0; mt < 2; mt++)
            ldsm_x4(a[mt], aBase + aRow[mt] + (((2 * ks + khA) ^ aSw[mt]) << 4));
#pragma unroll
        for (int p = 0; p < 2; p++)
            ldsm_x4(bb[p], bBase + bRow[p] + (((2 * ks + khB) ^ bSw[p]) << 4));
#pragma unroll
        for (int mt = 0; mt < 2; mt++)
#pragma unroll
            for (int nt = 0; nt < 4; nt++)
                mma_bf16(d[mt][nt], a[mt], bb[nt >> 1][(nt & 1) * 2],
                         bb[nt >> 1][(nt & 1) * 2 + 1]);
    }
}

// epilogue over one warp's 32x32 fragment; DIAG subtiles skip col stats
template <int PASS, bool DIAG>
__device__ __forceinline__ void epi_frag(
    const float (&d)[2][4][4], const int* labR, const int* labC,
    const int (&rowL)[4], const int (&colL)[8],
    const float* tpr, const float* tnr, const float* tpc, const float* tnc,
    float (&s0r)[4], float (&s1r)[4], float (&s0c)[8], float (&s1c)[8]) {
    int rl[4], cl[8];
#pragma unroll
    for (int i = 0; i < 4; i++) rl[i] = labR[rowL[i]];
#pragma unroll
    for (int j = 0; j < 8; j++) cl[j] = labC[colL[j]];
    float pR[4], nR[4], pC[8], nC[8];
    if (PASS == 1) {
#pragma unroll
        for (int i = 0; i < 4; i++) { pR[i] = tpr[rowL[i]]; nR[i] = tnr[rowL[i]]; }
        if (!DIAG)
#pragma unroll
            for (int j = 0; j < 8; j++) { pC[j] = tpc[colL[j]]; nC[j] = tnc[colL[j]]; }
    }
#pragma unroll
    for (int mt = 0; mt < 2; mt++)
#pragma unroll
        for (int nt = 0; nt < 4; nt++)
#pragma unroll
            for (int rix = 0; rix < 4; rix++) {
                const int i = mt * 2 + (rix >> 1);
                const int cj = nt * 2 + (rix & 1);
                const float sim = d[mt][nt][rix];
                const bool same = (rl[i] == cl[cj]);
                const bool self = DIAG && (rowL[i] == colL[cj]);
                if (PASS == 0) {
                    if (same) {
                        if (sim < ONE_M_EPS && !self) {
                            s0r[i] = fminf(s0r[i], sim);
                            if (!DIAG) s0c[cj] = fminf(s0c[cj], sim);
                        }
                    } else {
                        s1r[i] = fmaxf(s1r[i], sim);
                        if (!DIAG) s1c[cj] = fmaxf(s1c[cj], sim);
                    }
                } else {
                    const float e = ex2f(fmaf(sim, same ? A_POS : A_NEG,
                                              same ? B_POS : B_NEG));
                    if (same) {
                        if (!self) {
                            if (sim < pR[i]) s0r[i] += e;
                            if (!DIAG && sim < pC[cj]) s0c[cj] += e;
                        }
                    } else {
                        if (sim > nR[i]) s1r[i] += e;
                        if (!DIAG && sim > nC[cj]) s1c[cj] += e;
                    }
                }
            }
}

template <int PASS>
__device__ __forceinline__ void col_reduce(int PASSC, float (&s0c)[8], float (&s1c)[8],
                                           float* rc0, float* rc1,
                                           const int (&colL)[8], int wm, int lane) {
#pragma unroll
    for (int cj = 0; cj < 8; cj++) {
        float v0 = s0c[cj], v1 = s1c[cj];
#pragma unroll
        for (int m = 4; m <= 16; m <<= 1) {
            float o0 = __shfl_xor_sync(0xffffffff, v0, m);
            float o1 = __shfl_xor_sync(0xffffffff, v1, m);
            if (PASS == 0) { v0 = fminf(v0, o0); v1 = fmaxf(v1, o1); }
            else           { v0 += o0; v1 += o1; }
        }
        if (lane < 4) {
            rc0[wm * 128 + colL[cj]] = v0;
            rc1[wm * 128 + colL[cj]] = v1;
        }
    }
}

template <int PASS>
__global__ __launch_bounds__(THREADS, 1)
void ms_tri(const int* __restrict__ L, float* __restrict__ out) {
    extern __shared__ char smem[];
    const uint32_t sb = smem_to_u32(smem);
    const int tid = threadIdx.x;
    const int lane = tid & 31;
    const int w = tid >> 5;
    const int wm = w >> 2, wn = w & 3;   // 4x4 warp grid, 32x32 warp tile

    // static per-warp ldsm geometry (within a 128x128 subtile)
    uint32_t aRow[2], aSw[2], bRow[2], bSw[2];
    const int khA = lane >> 4;
    const int khB = (lane >> 3) & 1;
#pragma unroll
    for (int mt = 0; mt < 2; mt++) {
        int r = wm * 32 + mt * 16 + (lane & 15);
        aRow[mt] = r * 256;
        aSw[mt] = r & 7;
    }
#pragma unroll
    for (int p = 0; p < 2; p++) {
        int r = wn * 32 + p * 16 + ((lane >> 4) << 3) + (lane & 7);
        bRow[p] = r * 256;
        bSw[p] = r & 7;
    }
    int rowL[4], colL[8];
#pragma unroll
    for (int i = 0; i < 4; i++)
        rowL[i] = wm * 32 + (i >> 1) * 16 + (lane >> 2) + (i & 1) * 8;
#pragma unroll
    for (int cj = 0; cj < 8; cj++)
        colL[cj] = wn * 32 + (cj >> 1) * 8 + 2 * (lane & 3) + (cj & 1);

    const float* tpr = (const float*)(smem + OFF_TPR);
    const float* tnr = (const float*)(smem + OFF_TNR);
    const float* tpc = (const float*)(smem + OFF_TPC);
    const float* tnc = (const float*)(smem + OFF_TNC);
    const int* labA = (const int*)(smem + OFF_LABA);
    const int* labB = (const int*)(smem + OFF_LABB);
    float* rr0 = (float*)(smem + OFF_RR0);
    float* rr1 = (float*)(smem + OFF_RR1);
    float* rc0 = (float*)(smem + OFF_RC0);
    float* rc1 = (float*)(smem + OFF_RC1);

    {   // prologue prefetch
        int I, J;
        decode_st(blockIdx.x, I, J);
        prefetch_super(I, J, sb, L, tid);
    }
    CP_COMMIT();

    for (int st = blockIdx.x; st < NSUPER; st += GRID_MAIN) {
        int I, J;
        decode_st(st, I, J);
        const bool diagS = (I == J);
        const uint32_t aB = sb + OFF_A;
        const uint32_t bB = diagS ? (sb + OFF_A) : (sb + OFF_B);
        const int* labC = diagS ? labA : labB;

        CP_WAIT0();
        __syncthreads();   // tile data + labels visible; rr/rc free

        if (PASS == 1) {   // per-supertile thresholds
            if (tid < 256) {
                float mn = dec_f(g_min_enc[I * 256 + tid]);
                float mx = dec_f(g_max_enc[I * 256 + tid]);
                ((float*)(smem + OFF_TPR))[tid] = fminf(ONE_M_EPS, mx + MARGIN_F);
                ((float*)(smem + OFF_TNR))[tid] = mn - MARGIN_F;
            } else {
                int c = tid - 256;
                float mn = dec_f(g_min_enc[J * 256 + c]);
                float mx = dec_f(g_max_enc[J * 256 + c]);
                ((float*)(smem + OFF_TPC))[c] = fminf(ONE_M_EPS, mx + MARGIN_F);
                ((float*)(smem + OFF_TNC))[c] = mn - MARGIN_F;
            }
            __syncthreads();
        }

        // row stats persist across whole supertile; col stats per q-panel
        float s0r[2][4], s1r[2][4];
#pragma unroll
        for (int p = 0; p < 2; p++)
#pragma unroll
            for (int i = 0; i < 4; i++) {
                s0r[p][i] = (PASS == 0) ? inf_f() : 0.0f;
                s1r[p][i] = (PASS == 0) ? -inf_f() : 0.0f;
            }

        float d[2][4][4];
        // ----- q = 0 -----
        {
            float s0c[8], s1c[8];
#pragma unroll
            for (int j = 0; j < 8; j++) {
                s0c[j] = (PASS == 0) ? inf_f() : 0.0f;
                s1c[j] = (PASS == 0) ? -inf_f() : 0.0f;
            }
            // (p=0, q=0)
            gemm_sub(aB, bB, aRow, aSw, bRow, bSw, khA, khB, d);
            if (diagS)
                epi_frag<PASS, true>(d, labA, labC, rowL, colL,
                                     tpr, tnr, tpc, tnc, s0r[0], s1r[0], s0c, s1c);
            else
                epi_frag<PASS, false>(d, labA, labC, rowL, colL,
                                      tpr, tnr, tpc, tnc, s0r[0], s1r[0], s0c, s1c);
            // (p=1, q=0): skip if diag supertile (lower subtile)
            if (!diagS) {
                gemm_sub(aB + 32768, bB, aRow, aSw, bRow, bSw, khA, khB, d);
                epi_frag<PASS, false>(d, labA + 128, labC, rowL, colL,
                                      tpr + 128, tnr + 128, tpc, tnc,
                                      s0r[1], s1r[1], s0c, s1c);
            }
            col_reduce<PASS>(PASS, s0c, s1c, rc0, rc1, colL, wm, lane);
        }
        // ----- q = 1 -----
        {
            float s0c[8], s1c[8];
#pragma unroll
            for (int j = 0; j < 8; j++) {
                s0c[j] = (PASS == 0) ? inf_f() : 0.0f;
                s1c[j] = (PASS == 0) ? -inf_f() : 0.0f;
            }
            // (p=0, q=1): always off-diagonal
            gemm_sub(aB, bB + 32768, aRow, aSw, bRow, bSw, khA, khB, d);
            epi_frag<PASS, false>(d, labA, labC + 128, rowL, colL,
                                  tpr, tnr, tpc + 128, tnc + 128,
                                  s0r[0], s1r[0], s0c, s1c);
            // (p=1, q=1)
            gemm_sub(aB + 32768, bB + 32768, aRow, aSw, bRow, bSw, khA, khB, d);
            if (diagS)
                epi_frag<PASS, true>(d, labA + 128, labC + 128, rowL, colL,
                                     tpr + 128, tnr + 128, tpc + 128, tnc + 128,
                                     s0r[1], s1r[1], s0c, s1c);
            else
                epi_frag<PASS, false>(d, labA + 128, labC + 128, rowL, colL,
                                      tpr + 128, tnr + 128, tpc + 128, tnc + 128,
                                      s0r[1], s1r[1], s0c, s1c);
            col_reduce<PASS>(PASS, s0c, s1c, rc0 + 512, rc1 + 512, colL, wm, lane);
        }

        // row shfl reduce -> rr
#pragma unroll
        for (int p = 0; p < 2; p++)
#pragma unroll
            for (int i = 0; i < 4; i++) {
                float v0 = s0r[p][i], v1 = s1r[p][i];
#pragma unroll
                for (int m = 1; m <= 2; m <<= 1) {
                    float o0 = __shfl_xor_sync(0xffffffff, v0, m);
                    float o1 = __shfl_xor_sync(0xffffffff, v1, m);
                    if (PASS == 0) { v0 = fminf(v0, o0); v1 = fmaxf(v1, o1); }
                    else           { v0 += o0; v1 += o1; }
                }
                if ((lane & 3) == 0) {
                    rr0[p * 512 + wn * 128 + rowL[i]] = v0;
                    rr1[p * 512 + wn * 128 + rowL[i]] = v1;
                }
            }
        __syncthreads();   // reductions written; all warps done reading tiles

        if (st + GRID_MAIN < NSUPER) {   // overlap next loads with atomics
            int I2, J2;
            decode_st(st + GRID_MAIN, I2, J2);
            prefetch_super(I2, J2, sb, L, tid);
        }
        CP_COMMIT();

        if (tid < 256) {   // rows
            int p = tid >> 7, r = tid & 127;
            const float* b0 = rr0 + p * 512 + r;
            const float* b1 = rr1 + p * 512 + r;
            if (PASS == 0) {
                float mn = fminf(fminf(b0[0], b0[128]), fminf(b0[256], b0[384]));
                float mx = fmaxf(fmaxf(b1[0], b1[128]), fmaxf(b1[256], b1[384]));
                atomicMin(&g_min_enc[I * 256 + tid], enc_f(mn));
                atomicMax(&g_max_enc[I * 256 + tid], enc_f(mx));
            } else {
                atomicAdd(&g_possum[I * 256 + tid], b0[0] + b0[128] + b0[256] + b0[384]);
                atomicAdd(&g_negsum[I * 256 + tid], b1[0] + b1[128] + b1[256] + b1[384]);
            }
        } else {           // cols (diag supertile q=0 entries are identity: no-ops)
            int c = tid - 256;
            int q = c >> 7, cl = c & 127;
            const float* b0 = rc0 + q * 512 + cl;
            const float* b1 = rc1 + q * 512 + cl;
            if (PASS == 0) {
                float mn = fminf(fminf(b0[0], b0[128]), fminf(b0[256], b0[384]));
                float mx = fmaxf(fmaxf(b1[0], b1[128]), fmaxf(b1[256], b1[384]));
                atomicMin(&g_min_enc[J * 256 + c], enc_f(mn));
                atomicMax(&g_max_enc[J * 256 + c], enc_f(mx));
            } else {
                atomicAdd(&g_possum[J * 256 + c], b0[0] + b0[128] + b0[256] + b0[384]);
                atomicAdd(&g_negsum[J * 256 + c], b1[0] + b1[128] + b1[256] + b1[384]);
            }
        }
    }

    // ----- pass 1: fused finalize (last CTA) -----
    if (PASS == 1) {
        __shared__ unsigned rank;
        __threadfence();
        __syncthreads();
        if (tid == 0) rank = atomicAdd(&g_done, 1u);
        __syncthreads();
        if (rank == GRID_MAIN - 1) {
            __threadfence();
            float local = 0.0f;
            for (int r = tid; r < BATCH; r += THREADS) {
                float mn = dec_f(g_min_enc[r]);
                float mx = dec_f(g_max_enc[r]);
                if (mn < inf_f() && mx > -inf_f() && (mn - MARGIN_F < mx))
                    local += 0.5f * log1pf(g_possum[r]) + 0.025f * log1pf(g_negsum[r]);
            }
#pragma unroll
            for (int m = 16; m > 0; m >>= 1)
                local += __shfl_xor_sync(0xffffffff, local, m);
            float* red = (float*)(smem + OFF_RR0);
            if (lane == 0) red[w] = local;
            __syncthreads();
            if (tid == 0) {
                float tot = 0.0f;
#pragma unroll
                for (int i = 0; i < 16; i++) tot += red[i];
                out[0] = tot;
            }
        }
    }
}

extern "C" void kernel_launch(void* const* d_in, const int* in_sizes, int n_in,
                              void* d_out, int out_size) {
    const float* F = (const float*)d_in[0];
    const int* L = (const int*)d_in[1];
    if (n_in >= 2 && in_sizes[0] == BATCH) {  // defensive: inputs swapped
        F = (const float*)d_in[1];
        L = (const int*)d_in[0];
    }

    cudaFuncSetAttribute(ms_tri<0>, cudaFuncAttributeMaxDynamicSharedMemorySize, SMEM_BYTES);
    cudaFuncSetAttribute(ms_tri<1>, cudaFuncAttributeMaxDynamicSharedMemorySize, SMEM_BYTES);

    prep_k<<<1024, 256>>>(F, (float*)d_out);
    ms_tri<0><<<GRID_MAIN, THREADS, SMEM_BYTES>>>(L, (float*)d_out);
    ms_tri<1><<<GRID_MAIN, THREADS, SMEM_BYTES>>>(L, (float*)d_out);
}